// round 13
// baseline (speedup 1.0000x reference)
#include <cuda_runtime.h>
#include <cuda_bf16.h>

// N=1, C=2, H=64, W=64, D=32, radius=(3,3,1), SIGMA_XY=5, SIGMA_IMG=0.1, WEIGHT=1
#define NH 64
#define NW 64
#define ND 32
#define NL (NH * NW * ND)      // 131072

#define TPB  256
#define NBLK 512               // block = (h=4, w=2, d=32) slab = 256 voxels, 1 voxel/thread

// smem tile: (10, 8, 32) float2, pow2 strides; td = gd directly.
#define TSTRH 256
#define TSTRW 32
#define TSIZE 2560             // 10*8*32; +1 pad element for the corner dz=1 read
#define NQUAD (TSIZE / 4)      // 640 float2-quads (4 elements each)

#define SENTINEL 1e19f
#define LOG2E 1.4426950408889634f

__device__ float    g_part[NBLK];
__device__ unsigned g_cnt = 0;   // last block resets to 0 (graph-replay safe)

__device__ __forceinline__ float ex2(float x) {   // guaranteed MUFU EX2
    float r;
    asm("ex2.approx.f32 %0, %1;" : "=f"(r) : "f"(x));
    return r;
}

__global__ __launch_bounds__(TPB, 4) void k_all(const float* __restrict__ y,
                                                const float* __restrict__ s,
                                                const float* __restrict__ spacing,
                                                float* __restrict__ out) {
    __shared__ float2 tile[TSIZE + 2];
    __shared__ float  warp_s[8];

    // block -> slab origin (16 h-slabs x 32 w-slabs)
    const int hbase = (blockIdx.x >> 5) << 2;   // 0,4,...,60
    const int wbase = (blockIdx.x & 31) << 1;   // 0,2,...,62

    // ---- vectorized tile loader: float4 gmem loads, STS.128 interleave ----
    // Quad q covers tile elements [4q, 4q+4) = one (th, tw, td4..td4+3) run.
    #pragma unroll
    for (int j = 0; j < 3; ++j) {
        const int q = threadIdx.x + j * TPB;
        if (q < NQUAD) {
            const int th  = q >> 6;             // 0..9  (64 quads per h-row)
            const int tw  = (q >> 3) & 7;       // 0..7
            const int td4 = (q & 7) << 2;       // 0,4,...,28
            const int gh  = hbase + th - 3;
            const int gw  = wbase + tw - 3;
            float4 q0 = make_float4(SENTINEL, 0.0f, SENTINEL, 0.0f);
            float4 q1 = q0;
            if (((unsigned)gh < NH) & ((unsigned)gw < NW)) {
                const int gidx = (gh * NW + gw) * ND + td4;    // 16B-aligned
                const float4 a = __ldg((const float4*)(s + gidx));
                const float4 b = __ldg((const float4*)(y + gidx));
                q0 = make_float4(a.x, b.x, a.y, b.y);
                q1 = make_float4(a.z, b.z, a.w, b.w);
            }
            float4* tp = (float4*)&tile[th * TSTRH + tw * TSTRW + td4];
            tp[0] = q0;
            tp[1] = q1;
        }
    }
    if (threadIdx.x == 0) tile[TSIZE] = make_float2(SENTINEL, 0.0f);  // corner pad
    __syncthreads();

    // thread -> voxel
    const int d  = threadIdx.x & 31;
    const int wl = (threadIdx.x >> 5) & 1;      // 0..1
    const int hl = threadIdx.x >> 6;            // 0..3
    const int w  = wbase + wl;
    const int h  = hbase + hl;
    const int tb = (hl + 3) * TSTRH + (wl + 3) * TSTRW + d;

    const float2 c0 = tile[tb];
    const float sp  = c0.x;
    const float y0p = c0.y;
    const float m   = 1.0f - 2.0f * y0p;        // 1 - dot = y0p + m*y0q  (C=2 softmax)

    const float sH = __ldg(spacing + 0);
    const float sW = __ldg(spacing + 1);
    const float sD = __ldg(spacing + 2);
    const float aH = sH * sH * (LOG2E / 50.0f);
    const float aW = sW * sW * (LOG2E / 50.0f);
    const float aD = sD * sD * (LOG2E / 50.0f);
    const float c2 = -50.0f * LOG2E;

    // Register-resident spatial constants: 16 distinct (|dh|,|dw|) combos;
    // the dz=1 factor 2^(-aD) is hoisted out of the loop (scaleZ below).
    float coffs[16];
    #pragma unroll
    for (int ih = 0; ih < 4; ++ih) {
        const float vH = -aH * (float)(ih * ih);
        #pragma unroll
        for (int iw = 0; iw < 4; ++iw)
            coffs[ih * 4 + iw] = fmaf(-aW, (float)(iw * iw), vH);
    }

    // dz=0 taps -> Ka/KYa (always valid). dz=1 taps -> Kb/KYb (valid iff d<31;
    // d=31's dz=1 reads are the analytic-OOB set, masked exactly below).
    float Ka = 0.0f, KYa = 0.0f, Kb = 0.0f, KYb = 0.0f;

    // Half-space offsets (73 of 146 non-center taps); each in-bounds pair
    // counted once, doubled below (k and (1-dot) are p<->q symmetric).
    // Sentinel halo (h/w OOB rows) drives ex2 -> exactly 0: branch-free LDS.
    #pragma unroll
    for (int dz = 0; dz <= 1; ++dz) {
        #pragma unroll
        for (int dw = -3; dw <= 3; ++dw) {
            #pragma unroll
            for (int dh = -3; dh <= 3; ++dh) {
                if (dz == 0 && (dw < 0 || (dw == 0 && dh <= 0))) continue;
                const int ih = dh < 0 ? -dh : dh;           // compile-time
                const int iw = dw < 0 ? -dw : dw;           // compile-time
                const float2 cq = tile[tb + dh * TSTRH + dw * TSTRW + dz];
                const float ds = sp - cq.x;
                const float e2 = fmaf(c2 * ds, ds, coffs[ih * 4 + iw]);
                const float k  = ex2(e2);
                if (dz == 0) { Ka += k; KYa = fmaf(k, cq.y, KYa); }
                else         { Kb += k; KYb = fmaf(k, cq.y, KYb); }
            }
        }
    }
    const float maskD = (d < ND - 1) ? 1.0f : 0.0f;
    const float scaleZ = maskD * ex2(-aD);      // dz=1 spatial factor, hoisted
    const float K  = fmaf(scaleZ, Kb,  Ka);
    const float KY = fmaf(scaleZ, KYb, KYa);
    float acc = 2.0f * (y0p * K + m * KY);

    // OOB taps (zero-padded unfold): y-term 0; kernel value identical per
    // OOB offset: exp(-0.5*||f(p)||^2). Count analytically.
    const int cntH = min(h, 3) + min(NH - 1 - h, 3) + 1;
    const int cntW = min(w, 3) + min(NW - 1 - w, 3) + 1;
    const int cntD = min(d, 1) + min(ND - 1 - d, 1) + 1;
    const int noob = 147 - cntH * cntW * cntD;
    if (noob) {
        const float e = -(aH * (float)(h * h) + aW * (float)(w * w) + aD * (float)(d * d))
                        + c2 * sp * sp;
        acc = fmaf((float)noob, ex2(e), acc);
    }

    // ---- block reduction ----
    #pragma unroll
    for (int o = 16; o; o >>= 1) acc += __shfl_down_sync(0xffffffffu, acc, o);
    const int lane = threadIdx.x & 31;
    const int wrp  = threadIdx.x >> 5;
    if (lane == 0) warp_s[wrp] = acc;
    __syncthreads();
    if (threadIdx.x == 0) {
        float b = 0.0f;
        #pragma unroll
        for (int jj = 0; jj < 8; ++jj) b += warp_s[jj];
        g_part[blockIdx.x] = b;
    }

    // ---- last-block final reduction ----
    __threadfence();
    __shared__ bool is_last;
    if (threadIdx.x == 0)
        is_last = (atomicAdd(&g_cnt, 1u) == NBLK - 1);
    __syncthreads();

    if (is_last) {
        float v = g_part[threadIdx.x] + g_part[threadIdx.x + 256];
        #pragma unroll
        for (int o = 16; o; o >>= 1) v += __shfl_down_sync(0xffffffffu, v, o);
        if (lane == 0) warp_s[wrp] = v;
        __syncthreads();
        if (threadIdx.x == 0) {
            float t = 0.0f;
            #pragma unroll
            for (int jj = 0; jj < 8; ++jj) t += warp_s[jj];
            out[0] = t * (1.0f / (float)NL);
            g_cnt = 0;                 // restore for next graph replay
        }
    }
}

extern "C" void kernel_launch(void* const* d_in, const int* in_sizes, int n_in,
                              void* d_out, int out_size) {
    const float* y       = (const float*)d_in[0];  // (1,2,64,64,32) softmax; ch 0 used
    const float* sample  = (const float*)d_in[1];  // (1,1,64,64,32)
    const float* spacing = (const float*)d_in[2];  // (3,1)
    k_all<<<NBLK, TPB>>>(y, sample, spacing, (float*)d_out);
}

// round 14
// speedup vs baseline: 1.2077x; 1.2077x over previous
#include <cuda_runtime.h>
#include <cuda_bf16.h>

// N=1, C=2, H=64, W=64, D=32, radius=(3,3,1), SIGMA_XY=5, SIGMA_IMG=0.1, WEIGHT=1
#define NH 64
#define NW 64
#define ND 32
#define NL (NH * NW * ND)      // 131072

#define TPB  128
#define NBLK 1024              // block = (h=2, w=2, d=32) slab = 128 voxels, 1 voxel/thread

// smem tile: (8, 8, 32) float2, pow2 strides; td = gd directly.
#define TSTRH 256
#define TSTRW 32
#define TSIZE 2048             // 8*8*32; +pad for the corner dz=1 read
#define NQUAD (TSIZE / 4)      // 512 quads: exactly 4 iterations of 128 threads

#define SENTINEL 1e19f
#define LOG2E 1.4426950408889634f

__device__ float    g_part[NBLK];
__device__ unsigned g_cnt = 0;   // last block resets to 0 (graph-replay safe)

__device__ __forceinline__ float ex2(float x) {   // guaranteed MUFU EX2
    float r;
    asm("ex2.approx.f32 %0, %1;" : "=f"(r) : "f"(x));
    return r;
}

__global__ __launch_bounds__(TPB, 8) void k_all(const float* __restrict__ y,
                                                const float* __restrict__ s,
                                                const float* __restrict__ spacing,
                                                float* __restrict__ out) {
    __shared__ float2 tile[TSIZE + 2];
    __shared__ float  warp_s[4];

    // block -> slab origin (32 x 32 grid of 2x2 slabs)
    const int hbase = (blockIdx.x >> 5) << 1;   // 0,2,...,62
    const int wbase = (blockIdx.x & 31) << 1;   // 0,2,...,62

    // ---- vectorized tile loader: 512 quads = 4 full passes of 128 threads ----
    // Quad q = 4 float2 tile elements (one 16-float2-aligned d-run); per quad:
    // 2x LDG.128 (s, y) + 2x STS.128, pow2 index math, h/w halo predicate only.
    #pragma unroll
    for (int j = 0; j < 4; ++j) {
        const int q   = threadIdx.x + j * TPB;  // 0..511, no bounds check
        const int th  = q >> 6;                 // 0..7
        const int tw  = (q >> 3) & 7;           // 0..7
        const int td4 = (q & 7) << 2;           // 0,4,...,28
        const int gh  = hbase + th - 3;
        const int gw  = wbase + tw - 3;
        float4 q0 = make_float4(SENTINEL, 0.0f, SENTINEL, 0.0f);
        float4 q1 = q0;
        if (((unsigned)gh < NH) & ((unsigned)gw < NW)) {
            const int gidx = (gh * NW + gw) * ND + td4;    // 16B-aligned
            const float4 a = __ldg((const float4*)(s + gidx));
            const float4 b = __ldg((const float4*)(y + gidx));
            q0 = make_float4(a.x, b.x, a.y, b.y);
            q1 = make_float4(a.z, b.z, a.w, b.w);
        }
        float4* tp = (float4*)&tile[th * TSTRH + tw * TSTRW + td4];
        tp[0] = q0;
        tp[1] = q1;
    }
    if (threadIdx.x == 0) tile[TSIZE] = make_float2(SENTINEL, 0.0f);  // corner pad
    __syncthreads();

    // thread -> voxel
    const int d  = threadIdx.x & 31;
    const int wl = (threadIdx.x >> 5) & 1;      // 0..1
    const int hl = threadIdx.x >> 6;            // 0..1
    const int w  = wbase + wl;
    const int h  = hbase + hl;
    const int tb = (hl + 3) * TSTRH + (wl + 3) * TSTRW + d;

    const float2 c0 = tile[tb];
    const float sp  = c0.x;
    const float y0p = c0.y;
    const float m   = 1.0f - 2.0f * y0p;        // 1 - dot = y0p + m*y0q  (C=2 softmax)

    const float sH = __ldg(spacing + 0);
    const float sW = __ldg(spacing + 1);
    const float sD = __ldg(spacing + 2);
    const float aH = sH * sH * (LOG2E / 50.0f);
    const float aW = sW * sW * (LOG2E / 50.0f);
    const float aD = sD * sD * (LOG2E / 50.0f);
    const float c2 = -50.0f * LOG2E;

    // Register-resident spatial constants: 16 distinct (|dh|,|dw|) combos;
    // the dz=1 factor 2^(-aD) is hoisted out of the loop (scaleZ below).
    float coffs[16];
    #pragma unroll
    for (int ih = 0; ih < 4; ++ih) {
        const float vH = -aH * (float)(ih * ih);
        #pragma unroll
        for (int iw = 0; iw < 4; ++iw)
            coffs[ih * 4 + iw] = fmaf(-aW, (float)(iw * iw), vH);
    }

    // dz=0 taps -> Ka/KYa (always valid). dz=1 taps -> Kb/KYb (valid iff d<31;
    // d=31's dz=1 reads are the analytic-OOB set, masked exactly below).
    float Ka = 0.0f, KYa = 0.0f, Kb = 0.0f, KYb = 0.0f;

    // Half-space offsets (73 of 146 non-center taps); each in-bounds pair
    // counted once, doubled below (k and (1-dot) are p<->q symmetric).
    // Sentinel halo (h/w OOB rows) drives ex2 -> exactly 0: branch-free LDS.
    #pragma unroll
    for (int dz = 0; dz <= 1; ++dz) {
        #pragma unroll
        for (int dw = -3; dw <= 3; ++dw) {
            #pragma unroll
            for (int dh = -3; dh <= 3; ++dh) {
                if (dz == 0 && (dw < 0 || (dw == 0 && dh <= 0))) continue;
                const int ih = dh < 0 ? -dh : dh;           // compile-time
                const int iw = dw < 0 ? -dw : dw;           // compile-time
                const float2 cq = tile[tb + dh * TSTRH + dw * TSTRW + dz];
                const float ds = sp - cq.x;
                const float e2 = fmaf(c2 * ds, ds, coffs[ih * 4 + iw]);
                const float k  = ex2(e2);
                if (dz == 0) { Ka += k; KYa = fmaf(k, cq.y, KYa); }
                else         { Kb += k; KYb = fmaf(k, cq.y, KYb); }
            }
        }
    }
    const float maskD = (d < ND - 1) ? 1.0f : 0.0f;
    const float scaleZ = maskD * ex2(-aD);      // dz=1 spatial factor, hoisted
    const float K  = fmaf(scaleZ, Kb,  Ka);
    const float KY = fmaf(scaleZ, KYb, KYa);
    float acc = 2.0f * (y0p * K + m * KY);

    // OOB taps (zero-padded unfold): y-term 0; kernel value identical per
    // OOB offset: exp(-0.5*||f(p)||^2). Count analytically.
    const int cntH = min(h, 3) + min(NH - 1 - h, 3) + 1;
    const int cntW = min(w, 3) + min(NW - 1 - w, 3) + 1;
    const int cntD = min(d, 1) + min(ND - 1 - d, 1) + 1;
    const int noob = 147 - cntH * cntW * cntD;
    if (noob) {
        const float e = -(aH * (float)(h * h) + aW * (float)(w * w) + aD * (float)(d * d))
                        + c2 * sp * sp;
        acc = fmaf((float)noob, ex2(e), acc);
    }

    // ---- block reduction ----
    #pragma unroll
    for (int o = 16; o; o >>= 1) acc += __shfl_down_sync(0xffffffffu, acc, o);
    const int lane = threadIdx.x & 31;
    const int wrp  = threadIdx.x >> 5;
    if (lane == 0) warp_s[wrp] = acc;
    __syncthreads();
    if (threadIdx.x == 0)
        g_part[blockIdx.x] = (warp_s[0] + warp_s[1]) + (warp_s[2] + warp_s[3]);

    // ---- last-block final reduction ----
    __threadfence();
    __shared__ bool is_last;
    if (threadIdx.x == 0)
        is_last = (atomicAdd(&g_cnt, 1u) == NBLK - 1);
    __syncthreads();

    if (is_last) {
        float v = 0.0f;
        #pragma unroll
        for (int j = 0; j < NBLK / TPB; ++j)
            v += g_part[threadIdx.x + j * TPB];
        #pragma unroll
        for (int o = 16; o; o >>= 1) v += __shfl_down_sync(0xffffffffu, v, o);
        if (lane == 0) warp_s[wrp] = v;
        __syncthreads();
        if (threadIdx.x == 0) {
            out[0] = ((warp_s[0] + warp_s[1]) + (warp_s[2] + warp_s[3])) * (1.0f / (float)NL);
            g_cnt = 0;                 // restore for next graph replay
        }
    }
}

extern "C" void kernel_launch(void* const* d_in, const int* in_sizes, int n_in,
                              void* d_out, int out_size) {
    const float* y       = (const float*)d_in[0];  // (1,2,64,64,32) softmax; ch 0 used
    const float* sample  = (const float*)d_in[1];  // (1,1,64,64,32)
    const float* spacing = (const float*)d_in[2];  // (3,1)
    k_all<<<NBLK, TPB>>>(y, sample, spacing, (float*)d_out);
}

// round 15
// speedup vs baseline: 1.2113x; 1.0030x over previous
#include <cuda_runtime.h>
#include <cuda_bf16.h>

// N=1, C=2, H=64, W=64, D=32, radius=(3,3,1), SIGMA_XY=5, SIGMA_IMG=0.1, WEIGHT=1
#define NH 64
#define NW 64
#define ND 32
#define NL (NH * NW * ND)      // 131072

#define TPB  128
#define NBLK 1024              // block = (h=2, w=2, d=32) slab = 128 voxels, 1 voxel/thread

// smem tile: (8, 8, 32) float2 (v, y0), pow2 strides; td = gd directly.
#define TSTRH 256
#define TSTRW 32
#define TSIZE 2048             // 8*8*32; +pad for the corner dz=1 read

#define SENTINEL 1e19f
#define LOG2E 1.4426950408889634f
// v = s * K1, K1 = sqrt(50 * log2(e));  exp2 image exponent = -(vp-vq)^2
#define K1 8.49321805761796f

__device__ float    g_part[NBLK];
__device__ unsigned g_cnt = 0;   // last block resets to 0 (graph-replay safe)

__device__ __forceinline__ float ex2(float x) {   // guaranteed MUFU EX2
    float r;
    asm("ex2.approx.f32 %0, %1;" : "=f"(r) : "f"(x));
    return r;
}

__global__ __launch_bounds__(TPB, 8) void k_all(const float* __restrict__ y,
                                                const float* __restrict__ s,
                                                const float* __restrict__ spacing,
                                                float* __restrict__ out) {
    __shared__ float2 tile[TSIZE + 2];
    __shared__ float  warp_s[4];

    // block -> slab origin (32 x 32 grid of 2x2 slabs)
    const int hbase = (blockIdx.x >> 5) << 1;   // 0,2,...,62
    const int wbase = (blockIdx.x & 31) << 1;   // 0,2,...,62

    // ---- vectorized tile loader: 512 quads = 4 full passes of 128 threads ----
    // Stores (v, y) with v = s*K1, so the tap loop needs no per-tap scaling mul.
    #pragma unroll
    for (int j = 0; j < 4; ++j) {
        const int q   = threadIdx.x + j * TPB;  // 0..511, no bounds check
        const int th  = q >> 6;                 // 0..7
        const int tw  = (q >> 3) & 7;           // 0..7
        const int td4 = (q & 7) << 2;           // 0,4,...,28
        const int gh  = hbase + th - 3;
        const int gw  = wbase + tw - 3;
        float4 q0 = make_float4(SENTINEL, 0.0f, SENTINEL, 0.0f);
        float4 q1 = q0;
        if (((unsigned)gh < NH) & ((unsigned)gw < NW)) {
            const int gidx = (gh * NW + gw) * ND + td4;    // 16B-aligned
            const float4 a = __ldg((const float4*)(s + gidx));
            const float4 b = __ldg((const float4*)(y + gidx));
            q0 = make_float4(a.x * K1, b.x, a.y * K1, b.y);
            q1 = make_float4(a.z * K1, b.z, a.w * K1, b.w);
        }
        float4* tp = (float4*)&tile[th * TSTRH + tw * TSTRW + td4];
        tp[0] = q0;
        tp[1] = q1;
    }
    if (threadIdx.x == 0) tile[TSIZE] = make_float2(SENTINEL, 0.0f);  // corner pad
    __syncthreads();

    // thread -> voxel
    const int d  = threadIdx.x & 31;
    const int wl = (threadIdx.x >> 5) & 1;      // 0..1
    const int hl = threadIdx.x >> 6;            // 0..1
    const int w  = wbase + wl;
    const int h  = hbase + hl;
    const int tb = (hl + 3) * TSTRH + (wl + 3) * TSTRW + d;

    const float2 c0 = tile[tb];
    const float vp  = c0.x;                     // = sp * K1
    const float y0p = c0.y;
    const float m   = 1.0f - 2.0f * y0p;        // 1 - dot = y0p + m*y0q  (C=2 softmax)

    const float sH = __ldg(spacing + 0);
    const float sW = __ldg(spacing + 1);
    const float sD = __ldg(spacing + 2);
    const float aH = sH * sH * (LOG2E / 50.0f);
    const float aW = sW * sW * (LOG2E / 50.0f);
    const float aD = sD * sD * (LOG2E / 50.0f);

    // Register-resident spatial constants: 16 distinct (|dh|,|dw|) combos;
    // the dz=1 factor 2^(-aD) is hoisted out of the loop (scaleZ below).
    float coffs[16];
    #pragma unroll
    for (int ih = 0; ih < 4; ++ih) {
        const float vH = -aH * (float)(ih * ih);
        #pragma unroll
        for (int iw = 0; iw < 4; ++iw)
            coffs[ih * 4 + iw] = fmaf(-aW, (float)(iw * iw), vH);
    }

    // dz=0 taps -> Ka/KYa (always valid). dz=1 taps -> Kb/KYb (valid iff d<31;
    // d=31's dz=1 reads are the analytic-OOB set, masked exactly below).
    float Ka = 0.0f, KYa = 0.0f, Kb = 0.0f, KYb = 0.0f;

    // Half-space offsets (73 of 146 non-center taps); each in-bounds pair
    // counted once, doubled below (k and (1-dot) are p<->q symmetric).
    // Sentinel halo (h/w OOB rows) drives ex2 -> exactly 0: branch-free LDS.
    // Per tap: LDS.64, FADD, FFMA(-dv,dv,coff), MUFU, FADD, FFMA = 6 slots.
    #pragma unroll
    for (int dz = 0; dz <= 1; ++dz) {
        #pragma unroll
        for (int dw = -3; dw <= 3; ++dw) {
            #pragma unroll
            for (int dh = -3; dh <= 3; ++dh) {
                if (dz == 0 && (dw < 0 || (dw == 0 && dh <= 0))) continue;
                const int ih = dh < 0 ? -dh : dh;           // compile-time
                const int iw = dw < 0 ? -dw : dw;           // compile-time
                const float2 cq = tile[tb + dh * TSTRH + dw * TSTRW + dz];
                const float dv = vp - cq.x;
                const float e2 = fmaf(-dv, dv, coffs[ih * 4 + iw]);
                const float k  = ex2(e2);
                if (dz == 0) { Ka += k; KYa = fmaf(k, cq.y, KYa); }
                else         { Kb += k; KYb = fmaf(k, cq.y, KYb); }
            }
        }
    }
    const float maskD = (d < ND - 1) ? 1.0f : 0.0f;
    const float scaleZ = maskD * ex2(-aD);      // dz=1 spatial factor, hoisted
    const float K  = fmaf(scaleZ, Kb,  Ka);
    const float KY = fmaf(scaleZ, KYb, KYa);
    float acc = 2.0f * (y0p * K + m * KY);

    // OOB taps (zero-padded unfold): y-term 0; kernel value identical per
    // OOB offset: exp(-0.5*||f(p)||^2). Count analytically.
    const int cntH = min(h, 3) + min(NH - 1 - h, 3) + 1;
    const int cntW = min(w, 3) + min(NW - 1 - w, 3) + 1;
    const int cntD = min(d, 1) + min(ND - 1 - d, 1) + 1;
    const int noob = 147 - cntH * cntW * cntD;
    if (noob) {
        const float e = fmaf(-vp, vp,
            -(aH * (float)(h * h) + aW * (float)(w * w) + aD * (float)(d * d)));
        acc = fmaf((float)noob, ex2(e), acc);
    }

    // ---- block reduction ----
    #pragma unroll
    for (int o = 16; o; o >>= 1) acc += __shfl_down_sync(0xffffffffu, acc, o);
    const int lane = threadIdx.x & 31;
    const int wrp  = threadIdx.x >> 5;
    if (lane == 0) warp_s[wrp] = acc;
    __syncthreads();
    if (threadIdx.x == 0)
        g_part[blockIdx.x] = (warp_s[0] + warp_s[1]) + (warp_s[2] + warp_s[3]);

    // ---- last-block final reduction ----
    __threadfence();
    __shared__ bool is_last;
    if (threadIdx.x == 0)
        is_last = (atomicAdd(&g_cnt, 1u) == NBLK - 1);
    __syncthreads();

    if (is_last) {
        float v = 0.0f;
        #pragma unroll
        for (int j = 0; j < NBLK / TPB; ++j)
            v += g_part[threadIdx.x + j * TPB];
        #pragma unroll
        for (int o = 16; o; o >>= 1) v += __shfl_down_sync(0xffffffffu, v, o);
        if (lane == 0) warp_s[wrp] = v;
        __syncthreads();
        if (threadIdx.x == 0) {
            out[0] = ((warp_s[0] + warp_s[1]) + (warp_s[2] + warp_s[3])) * (1.0f / (float)NL);
            g_cnt = 0;                 // restore for next graph replay
        }
    }
}

extern "C" void kernel_launch(void* const* d_in, const int* in_sizes, int n_in,
                              void* d_out, int out_size) {
    const float* y       = (const float*)d_in[0];  // (1,2,64,64,32) softmax; ch 0 used
    const float* sample  = (const float*)d_in[1];  // (1,1,64,64,32)
    const float* spacing = (const float*)d_in[2];  // (3,1)
    k_all<<<NBLK, TPB>>>(y, sample, spacing, (float*)d_out);
}